// round 3
// baseline (speedup 1.0000x reference)
#include <cuda_runtime.h>

#define BATCH 64
#define CH    128
#define TLEN  10000
#define T4    (TLEN / 4)     // 2500
#define TT    128            // time-tile (floats)
#define NT4   32             // float4 per tile row
#define P4    33             // tile row pitch in float4 (conflict-free)
#define GRP   8              // batches per L2 group (8 * 5.12MB = 41MB << L2)

// Scratch (allocation-free rule: __device__ globals)
__device__ float g_m[BATCH * TLEN];   // channel-mean per (b, t)
__device__ float g_S1[BATCH * CH];    // sum of y over time
__device__ float g_S2[BATCH * CH];    // sum of y^2 over time

__global__ void k0_zero() {
    int i = blockIdx.x * blockDim.x + threadIdx.x;
    if (i < BATCH * CH) { g_S1[i] = 0.f; g_S2[i] = 0.f; }
}

// One block = one (batch, 128-wide time tile). Full channel dim in SMEM.
// Phases: vectorized load (+ mean partials in registers) -> combine mean ->
// warp-per-channel stats with shuffle reduce.
__global__ void __launch_bounds__(256) k1_stats(const float4* __restrict__ x4,
                                                int b0) {
    extern __shared__ float4 sm4[];
    float4* tile = sm4;            // CH * P4
    float4* pm   = tile + CH * P4; // 8 * 32 mean partials
    float4* mrow = pm + 8 * 32;    // 32

    const int b    = b0 + blockIdx.y;
    const int t0   = blockIdx.x * TT;
    const int tid  = threadIdx.x;
    const int t4v  = min(NT4, (TLEN - t0) >> 2);  // valid float4 per row
    const int lane = tid & 31;
    const int cgrp = tid >> 5;
    const float4* xb = x4 + (size_t)b * CH * T4 + (t0 >> 2);

    // Load 128x128 tile as float4 (coalesced 512B per warp), accumulating the
    // cross-channel mean partial for this thread's 4 t-values in registers.
    float4 acc = make_float4(0.f, 0.f, 0.f, 0.f);
    #pragma unroll
    for (int p = 0; p < 16; ++p) {
        int c = p * 8 + cgrp;
        float4 v = make_float4(0.f, 0.f, 0.f, 0.f);
        if (lane < t4v) v = xb[(size_t)c * T4 + lane];
        tile[c * P4 + lane] = v;
        acc.x += v.x; acc.y += v.y; acc.z += v.z; acc.w += v.w;
    }
    pm[cgrp * 32 + lane] = acc;
    __syncthreads();

    // Combine 8 partials -> channel mean per t; store to g_m (float4-aligned:
    // b*TLEN and t0 are both multiples of 4).
    if (tid < 32) {
        float4 s = pm[tid];
        #pragma unroll
        for (int g = 1; g < 8; ++g) {
            float4 t = pm[g * 32 + tid];
            s.x += t.x; s.y += t.y; s.z += t.z; s.w += t.w;
        }
        const float r = 1.f / 128.f;
        s.x *= r; s.y *= r; s.z *= r; s.w *= r;
        mrow[tid] = s;
        if (tid < t4v)
            ((float4*)g_m)[(size_t)b * T4 + (t0 >> 2) + tid] = s;
    }
    __syncthreads();

    // Per-channel sums of y = x - m: warp w owns channels [w*16, w*16+16).
    // Row LDS.128 is contiguous -> conflict-free; mrow lives in registers.
    const int w = tid >> 5;
    const float4 m4 = mrow[lane];
    #pragma unroll
    for (int i = 0; i < 16; ++i) {
        int c = w * 16 + i;
        float4 v = tile[c * P4 + lane];
        float y0 = v.x - m4.x, y1 = v.y - m4.y;
        float y2 = v.z - m4.z, y3 = v.w - m4.w;   // padded lanes: 0 - 0 = 0
        float s1 = (y0 + y1) + (y2 + y3);
        float s2 = fmaf(y0, y0, fmaf(y1, y1, fmaf(y2, y2, y3 * y3)));
        #pragma unroll
        for (int off = 16; off; off >>= 1) {
            s1 += __shfl_xor_sync(0xffffffffu, s1, off);
            s2 += __shfl_xor_sync(0xffffffffu, s2, off);
        }
        if (lane == 0) {
            atomicAdd(&g_S1[b * CH + c], s1);
            atomicAdd(&g_S2[b * CH + c], s2);
        }
    }
}

// out = (x - m - mean) * inv. x read is an L2 hit (loaded by the adjacent
// k1 of the same group). Finalize (k2) folded in. Streaming hints keep L2
// clean for the next group's x.
__global__ void __launch_bounds__(256) k3_apply(const float4* __restrict__ x4,
                                                float4* __restrict__ out4,
                                                int b0) {
    const int row = b0 * CH + blockIdx.y;   // global b*CH + c
    const int b   = row >> 7;
    const int j   = blockIdx.x * blockDim.x + threadIdx.x;
    if (j >= T4) return;

    const float mean = g_S1[row] * (1.f / TLEN);
    const float var  = fmaf(-mean, mean, g_S2[row] * (1.f / TLEN));
    const float inv  = (var > 0.f) ? rsqrtf(var) : 1.f;
    const float bias = mean * inv;

    const float4 xv = __ldcs(&x4[(size_t)row * T4 + j]);
    const float4 mv = ((const float4*)g_m)[(size_t)b * T4 + j];
    float4 o;
    o.x = fmaf(xv.x - mv.x, inv, -bias);
    o.y = fmaf(xv.y - mv.y, inv, -bias);
    o.z = fmaf(xv.z - mv.z, inv, -bias);
    o.w = fmaf(xv.w - mv.w, inv, -bias);
    __stcs(&out4[(size_t)row * T4 + j], o);
}

extern "C" void kernel_launch(void* const* d_in, const int* in_sizes, int n_in,
                              void* d_out, int out_size) {
    const float4* x4  = (const float4*)d_in[0];
    float4*       o4  = (float4*)d_out;

    const int smem_bytes = (CH * P4 + 8 * 32 + 32) * (int)sizeof(float4); // 72192
    cudaFuncSetAttribute(k1_stats, cudaFuncAttributeMaxDynamicSharedMemorySize,
                         smem_bytes);

    k0_zero<<<(BATCH * CH + 255) / 256, 256>>>();

    // Adjacent k1/k3 pairs per 8-batch group: k3's x-read hits L2.
    for (int g = 0; g < BATCH / GRP; ++g) {
        k1_stats<<<dim3((TLEN + TT - 1) / TT, GRP), 256, smem_bytes>>>(x4, g * GRP);
        k3_apply<<<dim3((T4 + 255) / 256, GRP * CH), 256>>>(x4, o4, g * GRP);
    }
}

// round 4
// speedup vs baseline: 1.0105x; 1.0105x over previous
#include <cuda_runtime.h>

#define BATCH 64
#define CH    128
#define TLEN  10000
#define T4    (TLEN / 4)     // 2500
#define TT    128            // time-tile (floats)
#define NT4   32             // float4 per tile row
#define P4    33             // tile row pitch in float4 (conflict-free)
#define GRP   8              // batches per L2 group (8 * 5.12MB = 41MB << L2)

// Scratch (allocation-free rule: __device__ globals)
__device__ float g_m[BATCH * TLEN];   // channel-mean per (b, t)
__device__ float g_S1[BATCH * CH];    // sum of y over time
__device__ float g_S2[BATCH * CH];    // sum of y^2 over time

__global__ void k0_zero() {
    int i = blockIdx.x * blockDim.x + threadIdx.x;
    if (i < BATCH * CH) { g_S1[i] = 0.f; g_S2[i] = 0.f; }
}

// One block = one (batch, 128-wide time tile). Full channel dim in SMEM.
// Phases: vectorized load (+ mean partials in registers) -> combine mean ->
// warp-per-channel stats with shuffle reduce.
__global__ void __launch_bounds__(256) k1_stats(const float4* __restrict__ x4,
                                                int b0) {
    extern __shared__ float4 sm4[];
    float4* tile = sm4;            // CH * P4
    float4* pm   = tile + CH * P4; // 8 * 32 mean partials
    float4* mrow = pm + 8 * 32;    // 32

    const int b    = b0 + blockIdx.y;
    const int t0   = blockIdx.x * TT;
    const int tid  = threadIdx.x;
    const int t4v  = min(NT4, (TLEN - t0) >> 2);  // valid float4 per row
    const int lane = tid & 31;
    const int cgrp = tid >> 5;
    const float4* xb = x4 + (size_t)b * CH * T4 + (t0 >> 2);

    // Load 128x128 tile as float4 (coalesced 512B per warp), accumulating the
    // cross-channel mean partial for this thread's 4 t-values in registers.
    float4 acc = make_float4(0.f, 0.f, 0.f, 0.f);
    #pragma unroll
    for (int p = 0; p < 16; ++p) {
        int c = p * 8 + cgrp;
        float4 v = make_float4(0.f, 0.f, 0.f, 0.f);
        if (lane < t4v) v = xb[(size_t)c * T4 + lane];
        tile[c * P4 + lane] = v;
        acc.x += v.x; acc.y += v.y; acc.z += v.z; acc.w += v.w;
    }
    pm[cgrp * 32 + lane] = acc;
    __syncthreads();

    // Combine 8 partials -> channel mean per t; store to g_m (float4-aligned:
    // b*TLEN and t0 are both multiples of 4).
    if (tid < 32) {
        float4 s = pm[tid];
        #pragma unroll
        for (int g = 1; g < 8; ++g) {
            float4 t = pm[g * 32 + tid];
            s.x += t.x; s.y += t.y; s.z += t.z; s.w += t.w;
        }
        const float r = 1.f / 128.f;
        s.x *= r; s.y *= r; s.z *= r; s.w *= r;
        mrow[tid] = s;
        if (tid < t4v)
            ((float4*)g_m)[(size_t)b * T4 + (t0 >> 2) + tid] = s;
    }
    __syncthreads();

    // Per-channel sums of y = x - m: warp w owns channels [w*16, w*16+16).
    // Row LDS.128 is contiguous -> conflict-free; mrow lives in registers.
    const int w = tid >> 5;
    const float4 m4 = mrow[lane];
    #pragma unroll
    for (int i = 0; i < 16; ++i) {
        int c = w * 16 + i;
        float4 v = tile[c * P4 + lane];
        float y0 = v.x - m4.x, y1 = v.y - m4.y;
        float y2 = v.z - m4.z, y3 = v.w - m4.w;   // padded lanes: 0 - 0 = 0
        float s1 = (y0 + y1) + (y2 + y3);
        float s2 = fmaf(y0, y0, fmaf(y1, y1, fmaf(y2, y2, y3 * y3)));
        #pragma unroll
        for (int off = 16; off; off >>= 1) {
            s1 += __shfl_xor_sync(0xffffffffu, s1, off);
            s2 += __shfl_xor_sync(0xffffffffu, s2, off);
        }
        if (lane == 0) {
            atomicAdd(&g_S1[b * CH + c], s1);
            atomicAdd(&g_S2[b * CH + c], s2);
        }
    }
}

// out = (x - m - mean) * inv. x read is an L2 hit (loaded by the adjacent
// k1 of the same group). Finalize (k2) folded in. Streaming hints keep L2
// clean for the next group's x.
__global__ void __launch_bounds__(256) k3_apply(const float4* __restrict__ x4,
                                                float4* __restrict__ out4,
                                                int b0) {
    const int row = b0 * CH + blockIdx.y;   // global b*CH + c
    const int b   = row >> 7;
    const int j   = blockIdx.x * blockDim.x + threadIdx.x;
    if (j >= T4) return;

    const float mean = g_S1[row] * (1.f / TLEN);
    const float var  = fmaf(-mean, mean, g_S2[row] * (1.f / TLEN));
    const float inv  = (var > 0.f) ? rsqrtf(var) : 1.f;
    const float bias = mean * inv;

    const float4 xv = __ldcs(&x4[(size_t)row * T4 + j]);
    const float4 mv = ((const float4*)g_m)[(size_t)b * T4 + j];
    float4 o;
    o.x = fmaf(xv.x - mv.x, inv, -bias);
    o.y = fmaf(xv.y - mv.y, inv, -bias);
    o.z = fmaf(xv.z - mv.z, inv, -bias);
    o.w = fmaf(xv.w - mv.w, inv, -bias);
    __stcs(&out4[(size_t)row * T4 + j], o);
}

extern "C" void kernel_launch(void* const* d_in, const int* in_sizes, int n_in,
                              void* d_out, int out_size) {
    const float4* x4  = (const float4*)d_in[0];
    float4*       o4  = (float4*)d_out;

    const int smem_bytes = (CH * P4 + 8 * 32 + 32) * (int)sizeof(float4); // 72192
    cudaFuncSetAttribute(k1_stats, cudaFuncAttributeMaxDynamicSharedMemorySize,
                         smem_bytes);

    k0_zero<<<(BATCH * CH + 255) / 256, 256>>>();

    // Adjacent k1/k3 pairs per 8-batch group: k3's x-read hits L2.
    for (int g = 0; g < BATCH / GRP; ++g) {
        k1_stats<<<dim3((TLEN + TT - 1) / TT, GRP), 256, smem_bytes>>>(x4, g * GRP);
        k3_apply<<<dim3((T4 + 255) / 256, GRP * CH), 256>>>(x4, o4, g * GRP);
    }
}

// round 6
// speedup vs baseline: 1.0148x; 1.0042x over previous
#include <cuda_runtime.h>

#define BATCH 64
#define CH    128
#define TLEN  10000
#define T4    (TLEN / 4)     // 2500
#define TT    128            // time-tile (floats)
#define NT4   32             // float4 per tile row
#define P4    33             // tile row pitch in float4 (conflict-free)
#define GRP   8              // batches per L2 group (8 * 5.12MB = 41MB << L2)

// Scratch (allocation-free rule: __device__ globals)
__device__ float g_m[BATCH * TLEN];   // channel-mean per (b, t)
__device__ float g_S1[BATCH * CH];    // sum of y over time
__device__ float g_S2[BATCH * CH];    // sum of y^2 over time

__global__ void k0_zero() {
    int i = blockIdx.x * blockDim.x + threadIdx.x;
    if (i < BATCH * CH) { g_S1[i] = 0.f; g_S2[i] = 0.f; }
}

// One block = one (batch, 128-wide time tile). Full channel dim in SMEM.
// Phases: vectorized load (+ mean partials in registers) -> combine mean ->
// warp-per-channel stats with shuffle reduce.
__global__ void __launch_bounds__(256) k1_stats(const float4* __restrict__ x4,
                                                int b0) {
    extern __shared__ float4 sm4[];
    float4* tile = sm4;            // CH * P4
    float4* pm   = tile + CH * P4; // 8 * 32 mean partials
    float4* mrow = pm + 8 * 32;    // 32

    const int b    = b0 + blockIdx.y;
    const int t0   = blockIdx.x * TT;
    const int tid  = threadIdx.x;
    const int t4v  = min(NT4, (TLEN - t0) >> 2);  // valid float4 per row
    const int lane = tid & 31;
    const int cgrp = tid >> 5;
    const float4* xb = x4 + (size_t)b * CH * T4 + (t0 >> 2);

    // Load 128x128 tile as float4 (coalesced 512B per warp), accumulating the
    // cross-channel mean partial for this thread's 4 t-values in registers.
    float4 acc = make_float4(0.f, 0.f, 0.f, 0.f);
    #pragma unroll
    for (int p = 0; p < 16; ++p) {
        int c = p * 8 + cgrp;
        float4 v = make_float4(0.f, 0.f, 0.f, 0.f);
        if (lane < t4v) v = xb[(size_t)c * T4 + lane];
        tile[c * P4 + lane] = v;
        acc.x += v.x; acc.y += v.y; acc.z += v.z; acc.w += v.w;
    }
    pm[cgrp * 32 + lane] = acc;
    __syncthreads();

    // Combine 8 partials -> channel mean per t; store to g_m (float4-aligned:
    // b*TLEN and t0 are both multiples of 4).
    if (tid < 32) {
        float4 s = pm[tid];
        #pragma unroll
        for (int g = 1; g < 8; ++g) {
            float4 t = pm[g * 32 + tid];
            s.x += t.x; s.y += t.y; s.z += t.z; s.w += t.w;
        }
        const float r = 1.f / 128.f;
        s.x *= r; s.y *= r; s.z *= r; s.w *= r;
        mrow[tid] = s;
        if (tid < t4v)
            ((float4*)g_m)[(size_t)b * T4 + (t0 >> 2) + tid] = s;
    }
    __syncthreads();

    // Per-channel sums of y = x - m: warp w owns channels [w*16, w*16+16).
    // Row LDS.128 is contiguous -> conflict-free; mrow lives in registers.
    const int w = tid >> 5;
    const float4 m4 = mrow[lane];
    #pragma unroll
    for (int i = 0; i < 16; ++i) {
        int c = w * 16 + i;
        float4 v = tile[c * P4 + lane];
        float y0 = v.x - m4.x, y1 = v.y - m4.y;
        float y2 = v.z - m4.z, y3 = v.w - m4.w;   // padded lanes: 0 - 0 = 0
        float s1 = (y0 + y1) + (y2 + y3);
        float s2 = fmaf(y0, y0, fmaf(y1, y1, fmaf(y2, y2, y3 * y3)));
        #pragma unroll
        for (int off = 16; off; off >>= 1) {
            s1 += __shfl_xor_sync(0xffffffffu, s1, off);
            s2 += __shfl_xor_sync(0xffffffffu, s2, off);
        }
        if (lane == 0) {
            atomicAdd(&g_S1[b * CH + c], s1);
            atomicAdd(&g_S2[b * CH + c], s2);
        }
    }
}

// out = (x - m - mean) * inv. x read is an L2 hit (loaded by the adjacent
// k1 of the same group). Finalize (k2) folded in. Streaming hints keep L2
// clean for the next group's x.
__global__ void __launch_bounds__(256) k3_apply(const float4* __restrict__ x4,
                                                float4* __restrict__ out4,
                                                int b0) {
    const int row = b0 * CH + blockIdx.y;   // global b*CH + c
    const int b   = row >> 7;
    const int j   = blockIdx.x * blockDim.x + threadIdx.x;
    if (j >= T4) return;

    const float mean = g_S1[row] * (1.f / TLEN);
    const float var  = fmaf(-mean, mean, g_S2[row] * (1.f / TLEN));
    const float inv  = (var > 0.f) ? rsqrtf(var) : 1.f;
    const float bias = mean * inv;

    const float4 xv = __ldcs(&x4[(size_t)row * T4 + j]);
    const float4 mv = ((const float4*)g_m)[(size_t)b * T4 + j];
    float4 o;
    o.x = fmaf(xv.x - mv.x, inv, -bias);
    o.y = fmaf(xv.y - mv.y, inv, -bias);
    o.z = fmaf(xv.z - mv.z, inv, -bias);
    o.w = fmaf(xv.w - mv.w, inv, -bias);
    __stcs(&out4[(size_t)row * T4 + j], o);
}

extern "C" void kernel_launch(void* const* d_in, const int* in_sizes, int n_in,
                              void* d_out, int out_size) {
    const float4* x4  = (const float4*)d_in[0];
    float4*       o4  = (float4*)d_out;

    const int smem_bytes = (CH * P4 + 8 * 32 + 32) * (int)sizeof(float4); // 72192
    cudaFuncSetAttribute(k1_stats, cudaFuncAttributeMaxDynamicSharedMemorySize,
                         smem_bytes);

    k0_zero<<<(BATCH * CH + 255) / 256, 256>>>();

    // Adjacent k1/k3 pairs per 8-batch group: k3's x-read hits L2.
    for (int g = 0; g < BATCH / GRP; ++g) {
        k1_stats<<<dim3((TLEN + TT - 1) / TT, GRP), 256, smem_bytes>>>(x4, g * GRP);
        k3_apply<<<dim3((T4 + 255) / 256, GRP * CH), 256>>>(x4, o4, g * GRP);
    }
}